// round 3
// baseline (speedup 1.0000x reference)
#include <cuda_runtime.h>
#include <math.h>

// LIF recurrence: v = alpha*v + beta*c; s = (v>=1); v = s ? 0 : v
// T=2048 sequential steps, N=32768 independent neurons.
// Output layout: d_out[0 .. T*N)       = spikes   (T,N) fp32
//                d_out[T*N .. 2*T*N)   = voltages (T,N) fp32

#define LIF_T 2048
#define LIF_N 32768
#define UNROLL 8

__global__ __launch_bounds__(128, 8)
void lif_kernel(const float* __restrict__ currents,
                const float* __restrict__ v0,
                float* __restrict__ out)
{
    const int n = blockIdx.x * blockDim.x + threadIdx.x;  // neuron id, 0..N-1

    // exp(-1/20) computed in double, rounded to float
    const float alpha = 0.951229424500714f;   // exp(-0.05)
    const float beta  = 1.0f - alpha;         // 0.048770575499286

    float v = v0[n];

    const float* __restrict__ cp = currents + n;
    float* __restrict__ sp = out + n;                                // spikes
    float* __restrict__ vp = out + (size_t)LIF_T * LIF_N + n;        // voltages

    #pragma unroll 1
    for (int t = 0; t < LIF_T; t += UNROLL) {
        // Batch UNROLL independent streaming loads up front (MLP=UNROLL)
        float c[UNROLL];
        #pragma unroll
        for (int u = 0; u < UNROLL; u++) {
            c[u] = __ldcs(cp + (size_t)u * LIF_N);
        }
        cp += (size_t)UNROLL * LIF_N;

        // Serial recurrence over the unrolled window; streaming stores
        #pragma unroll
        for (int u = 0; u < UNROLL; u++) {
            v = fmaf(beta, c[u], alpha * v);
            const bool fired = (v >= 1.0f);
            const float s = fired ? 1.0f : 0.0f;
            v = fired ? 0.0f : v;
            __stcs(sp + (size_t)u * LIF_N, s);
            __stcs(vp + (size_t)u * LIF_N, v);
        }
        sp += (size_t)UNROLL * LIF_N;
        vp += (size_t)UNROLL * LIF_N;
    }
}

extern "C" void kernel_launch(void* const* d_in, const int* in_sizes, int n_in,
                              void* d_out, int out_size)
{
    const float* currents = (const float*)d_in[0];  // (T, N) fp32
    const float* v0       = (const float*)d_in[1];  // (N,)  fp32
    float* out            = (float*)d_out;          // (2, T, N) fp32

    const int threads = 128;
    const int blocks  = LIF_N / threads;            // 256 blocks, all co-resident
    lif_kernel<<<blocks, threads>>>(currents, v0, out);
}

// round 4
// speedup vs baseline: 1.5485x; 1.5485x over previous
#include <cuda_runtime.h>
#include <math.h>

// LIF recurrence: v = alpha*v + beta*c; s = (v>=1); v = s ? 0 : v
// T=2048 sequential steps, N=32768 independent neurons.
// Output layout: d_out[0 .. T*N)       = spikes   (T,N) fp32
//                d_out[T*N .. 2*T*N)   = voltages (T,N) fp32
//
// Latency-bound kernel (only 1024 warps on chip): saturate HBM purely via
// per-thread MLP. UNROLL=32 batched streaming loads -> ~4 MB in flight,
// matching the BW*latency product of GB300 HBM3e.

#define LIF_T 2048
#define LIF_N 32768
#define UNROLL 32

__global__ __launch_bounds__(128, 8)
void lif_kernel(const float* __restrict__ currents,
                const float* __restrict__ v0,
                float* __restrict__ out)
{
    const int n = blockIdx.x * blockDim.x + threadIdx.x;  // neuron id, 0..N-1

    const float alpha = 0.951229424500714f;   // exp(-0.05)
    const float beta  = 1.0f - alpha;

    float v = v0[n];

    const float* __restrict__ cp = currents + n;
    float* __restrict__ sp = out + n;                                // spikes
    float* __restrict__ vp = out + (size_t)LIF_T * LIF_N + n;        // voltages

    #pragma unroll 1
    for (int t = 0; t < LIF_T; t += UNROLL) {
        // Batch UNROLL independent streaming loads up front (MLP=UNROLL).
        // 32768 threads * 32 * 4B = 4 MB outstanding -> covers DRAM latency.
        float c[UNROLL];
        #pragma unroll
        for (int u = 0; u < UNROLL; u++) {
            c[u] = __ldcs(cp + (size_t)u * LIF_N);
        }
        cp += (size_t)UNROLL * LIF_N;

        // Serial recurrence over the unrolled window; streaming stores.
        #pragma unroll
        for (int u = 0; u < UNROLL; u++) {
            v = fmaf(beta, c[u], alpha * v);
            const bool fired = (v >= 1.0f);
            const float s = fired ? 1.0f : 0.0f;
            v = fired ? 0.0f : v;
            __stcs(sp + (size_t)u * LIF_N, s);
            __stcs(vp + (size_t)u * LIF_N, v);
        }
        sp += (size_t)UNROLL * LIF_N;
        vp += (size_t)UNROLL * LIF_N;
    }
}

extern "C" void kernel_launch(void* const* d_in, const int* in_sizes, int n_in,
                              void* d_out, int out_size)
{
    const float* currents = (const float*)d_in[0];  // (T, N) fp32
    const float* v0       = (const float*)d_in[1];  // (N,)  fp32
    float* out            = (float*)d_out;          // (2, T, N) fp32

    const int threads = 128;
    const int blocks  = LIF_N / threads;            // 256 blocks, all co-resident
    lif_kernel<<<blocks, threads>>>(currents, v0, out);
}